// round 10
// baseline (speedup 1.0000x reference)
#include <cuda_runtime.h>
#include <cstdint>

// ---------------------------------------------------------------------------
// GAT fused: out[M,256] = x[M,256] @ w_l^T + (sum_k w_k * neigh[M,k,256]) @ w_r^T
// A[M,512] @ B[512,256], A = [x | aggr], B rows = [w_l ; w_r].
//
// R9: TILE_M=128, THREADS=512 (R7 shape, max A-reuse) + R8's prepass/cp.async B.
//  - KC=16 -> A 2x8KB + B 2x16KB = 48KB static smem, truly double-buffered.
//  - B: cp.async from pre-swizzled tf32 image g_B (prepass kernel), 1 chunk ahead.
//  - A: LDG 2 chunks ahead (regs), weighted-sum+cvt+STS 1 chunk ahead.
//  - One __syncthreads + wait_group per chunk; no cudaFuncSetAttribute.
// ---------------------------------------------------------------------------

#define M_TOTAL  262144      // T*N
#define DIN      256
#define DOUT     256
#define KNB      5
#define TILE_M   128
#define KC       16          // K columns per chunk
#define NCH      32          // 512 / 16
#define THREADS  512

// Pre-converted, pre-swizzled B image: 32 chunks x (256 rows x 16 cols) tf32.
__device__ uint32_t g_B[NCH * DOUT * KC];   // 512 KB

__device__ __forceinline__ uint32_t f2tf32(float f) {
    uint32_t u;
    asm("cvt.rna.tf32.f32 %0, %1;" : "=r"(u) : "f"(f));
    return u;
}

__device__ __forceinline__ void mma_tf32(float* d,
                                         uint32_t a0, uint32_t a1, uint32_t a2, uint32_t a3,
                                         uint32_t b0, uint32_t b1) {
    asm volatile(
        "mma.sync.aligned.m16n8k8.row.col.f32.tf32.tf32.f32 "
        "{%0,%1,%2,%3}, {%4,%5,%6,%7}, {%8,%9}, {%0,%1,%2,%3};"
        : "+f"(d[0]), "+f"(d[1]), "+f"(d[2]), "+f"(d[3])
        : "r"(a0), "r"(a1), "r"(a2), "r"(a3), "r"(b0), "r"(b1));
}

// Swizzle within a 16-float row: float4 group g of row r stored at g ^ ((r>>1)&3).
// Fragment loads conflict-free: bank = 16*(grp&1) + 4*(g ^ (grp>>1)) + qid.
__device__ __forceinline__ int swz(int row, int col) {
    return row * KC + ((((col >> 2) ^ ((row >> 1) & 3)) << 2) | (col & 3));
}

__device__ __forceinline__ void cp_async16(uint32_t dst_smem, const void* src) {
    asm volatile("cp.async.cg.shared.global [%0], [%1], 16;"
                 :: "r"(dst_smem), "l"(src));
}

// ---- prepass: [w_l ; w_r] -> tf32, chunked + swizzled image in g_B ----
__global__ void __launch_bounds__(256)
gat_prep_kernel(const float* __restrict__ wl, const float* __restrict__ wr)
{
    const int gid = blockIdx.x * 256 + threadIdx.x;   // 0..32767, one float4 each
    const int c   = gid >> 10;          // chunk 0..31 (1024 float4 per chunk)
    const int rem = gid & 1023;
    const int n   = rem >> 2;           // row 0..255
    const int g   = rem & 3;            // float4 group 0..3
    const float* wsrc = (c < 16) ? wl : wr;
    float4 v = *(const float4*)(wsrc + (size_t)n * DIN + (c & 15) * KC + g * 4);
    uint4 pv = make_uint4(f2tf32(v.x), f2tf32(v.y), f2tf32(v.z), f2tf32(v.w));
    *(uint4*)&g_B[(size_t)c * (DOUT * KC) + swz(n, g * 4)] = pv;
}

// ---- main fused kernel ----
__global__ void __launch_bounds__(THREADS, 1)
gat_mma_kernel(const float* __restrict__ x, const float* __restrict__ neigh,
               const float* __restrict__ wag, float* __restrict__ out)
{
    __shared__ uint32_t sA[2][TILE_M * KC];   // 2 x 8 KB
    __shared__ uint32_t sB[2][DOUT * KC];     // 2 x 16 KB   -> 48 KB total

    const int tid  = threadIdx.x;
    const int lane = tid & 31;
    const int wid  = tid >> 5;           // 0..15
    const int grp  = lane >> 2;          // 0..7
    const int qid  = lane & 3;           // 0..3
    const int warpM = wid >> 2;          // 0..3 (32 rows each)
    const int warpN = wid & 3;           // 0..3 (64 cols each)

    const float w0 = wag[0], w1 = wag[1], w2 = wag[2], w3 = wag[3], w4 = wag[4];
    const size_t mbase = (size_t)blockIdx.x * TILE_M;

    // A loader mapping: one float4 per thread per chunk (128 rows x 4 groups)
    const int a_r = tid >> 2;            // row 0..127
    const int a_g = tid & 3;             // float4 group 0..3
    const uint32_t a_sts_off = (uint32_t)swz(a_r, a_g * 4);

    const float* xrow = x + (mbase + (size_t)a_r) * DIN + a_g * 4;
    const float* nrow = neigh + (mbase + (size_t)a_r) * (KNB * DIN) + a_g * 4;

    float4 pre[5];   // raw prefetched A data (x: pre[0]; neigh: pre[0..4])

    float acc[2][8][4];
    #pragma unroll
    for (int i = 0; i < 2; ++i)
        #pragma unroll
        for (int j = 0; j < 8; ++j)
            #pragma unroll
            for (int q = 0; q < 4; ++q)
                acc[i][j][q] = 0.f;

    auto ldgA = [&](int d) {
        if (d < 16) {
            pre[0] = *(const float4*)(xrow + d * KC);
        } else {
            const float4* np = (const float4*)(nrow + (d - 16) * KC);
            pre[0] = np[0];
            pre[1] = np[DIN / 4];
            pre[2] = np[2 * (DIN / 4)];
            pre[3] = np[3 * (DIN / 4)];
            pre[4] = np[4 * (DIN / 4)];
        }
    };
    auto stsA = [&](int d, int buf) {
        float4 v;
        if (d < 16) {
            v = pre[0];
        } else {
            v.x = w0*pre[0].x + w1*pre[1].x + w2*pre[2].x + w3*pre[3].x + w4*pre[4].x;
            v.y = w0*pre[0].y + w1*pre[1].y + w2*pre[2].y + w3*pre[3].y + w4*pre[4].y;
            v.z = w0*pre[0].z + w1*pre[1].z + w2*pre[2].z + w3*pre[3].z + w4*pre[4].z;
            v.w = w0*pre[0].w + w1*pre[1].w + w2*pre[2].w + w3*pre[3].w + w4*pre[4].w;
        }
        *(uint4*)&sA[buf][a_sts_off] =
            make_uint4(f2tf32(v.x), f2tf32(v.y), f2tf32(v.z), f2tf32(v.w));
    };
    auto cpB = [&](int d, int buf) {
        // 16 KB = 1024 float4; 512 threads -> 2 cp.async of 16B each.
        const uint32_t* src = g_B + (size_t)d * (DOUT * KC);
        uint32_t dst = (uint32_t)__cvta_generic_to_shared(&sB[buf][0]);
        cp_async16(dst + (uint32_t)tid * 16u, src + tid * 4);
        cp_async16(dst + (uint32_t)(tid + THREADS) * 16u, src + (tid + THREADS) * 4);
        asm volatile("cp.async.commit_group;" ::: "memory");
    };

    // ---- prologue ----
    ldgA(0);
    stsA(0, 0);
    cpB(0, 0);
    ldgA(1);

    // ---- main loop: one sync per chunk ----
    #pragma unroll 1
    for (int c = 0; c < NCH; ++c) {
        const int cur = c & 1, nxt = cur ^ 1;

        asm volatile("cp.async.wait_group 0;" ::: "memory");
        __syncthreads();                    // sA[cur], sB[cur] ready

        if (c + 1 < NCH) {
            cpB(c + 1, nxt);                // async into back buffer
            stsA(c + 1, nxt);               // regs (ldgA(c+1)) -> back buffer
        }
        if (c + 2 < NCH) ldgA(c + 2);       // LDGs fly under the MMAs below

        #pragma unroll
        for (int ks = 0; ks < 2; ++ks) {
            const int k0 = 8 * ks;
            uint32_t a[2][4];
            #pragma unroll
            for (int i = 0; i < 2; ++i) {
                const int r = warpM * 32 + i * 16 + grp;
                a[i][0] = sA[cur][swz(r,     k0 + qid)];
                a[i][1] = sA[cur][swz(r + 8, k0 + qid)];
                a[i][2] = sA[cur][swz(r,     k0 + qid + 4)];
                a[i][3] = sA[cur][swz(r + 8, k0 + qid + 4)];
            }
            #pragma unroll
            for (int j = 0; j < 8; ++j) {
                const int n = warpN * 64 + j * 8 + grp;
                const uint32_t b0 = sB[cur][swz(n, k0 + qid)];
                const uint32_t b1 = sB[cur][swz(n, k0 + qid + 4)];
                mma_tf32(acc[0][j], a[0][0], a[0][1], a[0][2], a[0][3], b0, b1);
                mma_tf32(acc[1][j], a[1][0], a[1][1], a[1][2], a[1][3], b0, b1);
            }
        }
        __syncthreads();                    // done reading cur before it is refilled
    }

    // ---- epilogue ----
    #pragma unroll
    for (int i = 0; i < 2; ++i) {
        const size_t row = mbase + warpM * 32 + i * 16 + grp;
        #pragma unroll
        for (int j = 0; j < 8; ++j) {
            const int col = warpN * 64 + j * 8 + qid * 2;
            *(float2*)&out[row * DOUT + col] =
                make_float2(acc[i][j][0], acc[i][j][1]);
            *(float2*)&out[(row + 8) * DOUT + col] =
                make_float2(acc[i][j][2], acc[i][j][3]);
        }
    }
}

extern "C" void kernel_launch(void* const* d_in, const int* in_sizes, int n_in,
                              void* d_out, int out_size) {
    const float* x     = (const float*)d_in[0];   // [T,N,256]
    const float* neigh = (const float*)d_in[1];   // [T,N,5,256]
    const float* wag   = (const float*)d_in[2];   // [1,5]
    const float* wl    = (const float*)d_in[3];   // [256,256]
    const float* wr    = (const float*)d_in[4];   // [256,256]
    float* out         = (float*)d_out;           // [M,256]

    gat_prep_kernel<<<128, 256>>>(wl, wr);
    gat_mma_kernel<<<M_TOTAL / TILE_M, THREADS>>>(x, neigh, wag, out);
}

// round 16
// speedup vs baseline: 1.0223x; 1.0223x over previous
#include <cuda_runtime.h>
#include <cstdint>

// ---------------------------------------------------------------------------
// GAT fused: out[M,256] = x[M,256] @ w_l^T + (sum_k w_k * neigh[M,k,256]) @ w_r^T
// A[M,512] @ B[512,256], A = [x | aggr], B rows = [w_l ; w_r].
//
// R12: mma.sync m16n8k8 tf32 (tcgen05 unavailable: harness targets sm_103).
//  - TILE_M=128, THREADS=512, KC=16, NCH=32; 48KB static smem:
//    sA[2][128x16] (2x8KB) + sB[2][256x16] (2x16KB), both double-buffered.
//  - B: prepass -> pre-swizzled tf32 image g_B -> cp.async, 1 chunk ahead.
//  - A: ONE float4 position per thread per chunk (20 prefetch regs max ->
//    no spills; this was R8/R9's regression cause), LDG 2 chunks ahead,
//    weighted-sum + cvt.rna + STS 1 chunk ahead.
//  - ONE __syncthreads per chunk: wait_group -> sync -> issue next -> compute.
// ---------------------------------------------------------------------------

#define M_TOTAL  262144      // T*N
#define DIN      256
#define DOUT     256
#define KNB      5
#define TILE_M   128
#define KC       16
#define NCH      32          // 512 / 16
#define THREADS  512

// Pre-converted, pre-swizzled B image: 32 chunks x (256 rows x 16 cols) tf32.
__device__ uint32_t g_B[NCH * DOUT * KC];   // 512 KB

__device__ __forceinline__ uint32_t f2tf32(float f) {
    uint32_t u;
    asm("cvt.rna.tf32.f32 %0, %1;" : "=r"(u) : "f"(f));
    return u;
}

__device__ __forceinline__ void mma_tf32(float* d,
                                         uint32_t a0, uint32_t a1, uint32_t a2, uint32_t a3,
                                         uint32_t b0, uint32_t b1) {
    asm volatile(
        "mma.sync.aligned.m16n8k8.row.col.f32.tf32.tf32.f32 "
        "{%0,%1,%2,%3}, {%4,%5,%6,%7}, {%8,%9}, {%0,%1,%2,%3};"
        : "+f"(d[0]), "+f"(d[1]), "+f"(d[2]), "+f"(d[3])
        : "r"(a0), "r"(a1), "r"(a2), "r"(a3), "r"(b0), "r"(b1));
}

// Swizzle within a 16-float row: float4 group g of row r stored at g ^ ((r>>1)&3).
// Fragment loads conflict-free: bank = 16*(r&1) + 4*(g ^ (grp>>1)) + qid.
__device__ __forceinline__ int swz(int row, int col) {
    return row * KC + ((((col >> 2) ^ ((row >> 1) & 3)) << 2) | (col & 3));
}

__device__ __forceinline__ void cp_async16(uint32_t dst_smem, const void* src) {
    asm volatile("cp.async.cg.shared.global [%0], [%1], 16;"
                 :: "r"(dst_smem), "l"(src));
}

// ---- prepass: [w_l ; w_r] -> tf32, chunked + swizzled image in g_B ----
__global__ void __launch_bounds__(256)
gat_prep_kernel(const float* __restrict__ wl, const float* __restrict__ wr)
{
    const int gid = blockIdx.x * 256 + threadIdx.x;   // 0..32767, one float4 each
    const int c   = gid >> 10;          // chunk 0..31 (1024 float4 per chunk)
    const int rem = gid & 1023;
    const int n   = rem >> 2;           // row 0..255
    const int g   = rem & 3;            // float4 group 0..3
    const float* wsrc = (c < 16) ? wl : wr;
    float4 v = *(const float4*)(wsrc + (size_t)n * DIN + (c & 15) * KC + g * 4);
    uint4 pv = make_uint4(f2tf32(v.x), f2tf32(v.y), f2tf32(v.z), f2tf32(v.w));
    *(uint4*)&g_B[(size_t)c * (DOUT * KC) + swz(n, g * 4)] = pv;
}

// ---- main fused kernel ----
__global__ void __launch_bounds__(THREADS, 1)
gat_mma_kernel(const float* __restrict__ x, const float* __restrict__ neigh,
               const float* __restrict__ wag, float* __restrict__ out)
{
    __shared__ uint32_t sA[2][TILE_M * KC];   // 2 x 8 KB
    __shared__ uint32_t sB[2][DOUT * KC];     // 2 x 16 KB   -> 48 KB total

    const int tid  = threadIdx.x;
    const int lane = tid & 31;
    const int wid  = tid >> 5;           // 0..15
    const int grp  = lane >> 2;          // 0..7
    const int qid  = lane & 3;           // 0..3
    const int warpM = wid >> 2;          // 0..3 (32 rows each)
    const int warpN = wid & 3;           // 0..3 (64 cols each)

    const float w0 = wag[0], w1 = wag[1], w2 = wag[2], w3 = wag[3], w4 = wag[4];
    const size_t mbase = (size_t)blockIdx.x * TILE_M;

    // A loader: ONE float4 position per thread per chunk (128 rows x 4 groups).
    const int a_r = tid >> 2;            // row 0..127
    const int a_g = tid & 3;             // float4 group 0..3
    const int a_sts = swz(a_r, a_g * 4);

    const float* xrow = x + (mbase + (size_t)a_r) * DIN + a_g * 4;
    const float* nrow = neigh + (mbase + (size_t)a_r) * (KNB * DIN) + a_g * 4;

    float4 pre[KNB];   // raw prefetched A (x chunks: pre[0]; neigh: pre[0..4])

    float acc[2][8][4];
    #pragma unroll
    for (int i = 0; i < 2; ++i)
        #pragma unroll
        for (int j = 0; j < 8; ++j)
            #pragma unroll
            for (int q = 0; q < 4; ++q)
                acc[i][j][q] = 0.f;

    auto ldgA = [&](int c) {
        if (c < 16) {
            pre[0] = *(const float4*)(xrow + c * KC);
        } else {
            const int d = (c - 16) * KC;
            #pragma unroll
            for (int k = 0; k < KNB; ++k)
                pre[k] = *(const float4*)(nrow + d + k * DIN);
        }
    };
    auto stsA = [&](int c, int buf) {
        float4 v;
        if (c < 16) {
            v = pre[0];
        } else {
            v.x = w0*pre[0].x + w1*pre[1].x + w2*pre[2].x + w3*pre[3].x + w4*pre[4].x;
            v.y = w0*pre[0].y + w1*pre[1].y + w2*pre[2].y + w3*pre[3].y + w4*pre[4].y;
            v.z = w0*pre[0].z + w1*pre[1].z + w2*pre[2].z + w3*pre[3].z + w4*pre[4].z;
            v.w = w0*pre[0].w + w1*pre[1].w + w2*pre[2].w + w3*pre[3].w + w4*pre[4].w;
        }
        *(uint4*)&sA[buf][a_sts] =
            make_uint4(f2tf32(v.x), f2tf32(v.y), f2tf32(v.z), f2tf32(v.w));
    };
    auto cpB = [&](int c, int buf) {
        // 16 KB = 1024 float4; 512 threads -> 2 cp.async of 16B each.
        const uint32_t* src = g_B + (size_t)c * (DOUT * KC);
        uint32_t dst = (uint32_t)__cvta_generic_to_shared(&sB[buf][0]);
        cp_async16(dst + (uint32_t)tid * 16u, src + tid * 4);
        cp_async16(dst + (uint32_t)(tid + THREADS) * 16u, src + (tid + THREADS) * 4);
        asm volatile("cp.async.commit_group;" ::: "memory");
    };

    // ---- prologue ----
    ldgA(0);
    stsA(0, 0);        // pre(0) -> sA[0]
    cpB(0, 0);         // group for chunk 0
    ldgA(1);           // pre = chunk 1

    // ---- main loop: ONE sync per chunk ----
    #pragma unroll 1
    for (int c = 0; c < NCH; ++c) {
        const int cur = c & 1, nxt = cur ^ 1;

        asm volatile("cp.async.wait_group 0;" ::: "memory");  // B(c) done (this thread)
        __syncthreads();   // B(c)+A(c) visible to all; compute(c-1) reads done

        if (c + 1 < NCH) {
            cpB(c + 1, nxt);        // async into back buffer
            stsA(c + 1, nxt);       // pre(c+1) -> back buffer
        }
        if (c + 2 < NCH) ldgA(c + 2);   // LDGs fly under the MMAs below

        #pragma unroll
        for (int ks = 0; ks < 2; ++ks) {
            const int k0 = 8 * ks;
            uint32_t a[2][4];
            #pragma unroll
            for (int i = 0; i < 2; ++i) {
                const int r = warpM * 32 + i * 16 + grp;
                a[i][0] = sA[cur][swz(r,     k0 + qid)];
                a[i][1] = sA[cur][swz(r + 8, k0 + qid)];
                a[i][2] = sA[cur][swz(r,     k0 + qid + 4)];
                a[i][3] = sA[cur][swz(r + 8, k0 + qid + 4)];
            }
            #pragma unroll
            for (int j = 0; j < 8; ++j) {
                const int n = warpN * 64 + j * 8 + grp;
                const uint32_t b0 = sB[cur][swz(n, k0 + qid)];
                const uint32_t b1 = sB[cur][swz(n, k0 + qid + 4)];
                mma_tf32(acc[0][j], a[0][0], a[0][1], a[0][2], a[0][3], b0, b1);
                mma_tf32(acc[1][j], a[1][0], a[1][1], a[1][2], a[1][3], b0, b1);
            }
        }
    }

    // ---- epilogue: m16n8 accumulator layout -> out ----
    #pragma unroll
    for (int i = 0; i < 2; ++i) {
        const size_t row = mbase + warpM * 32 + i * 16 + grp;
        #pragma unroll
        for (int j = 0; j < 8; ++j) {
            const int col = warpN * 64 + j * 8 + qid * 2;
            *(float2*)&out[row * DOUT + col] =
                make_float2(acc[i][j][0], acc[i][j][1]);
            *(float2*)&out[(row + 8) * DOUT + col] =
                make_float2(acc[i][j][2], acc[i][j][3]);
        }
    }
}

extern "C" void kernel_launch(void* const* d_in, const int* in_sizes, int n_in,
                              void* d_out, int out_size) {
    const float* x     = (const float*)d_in[0];   // [T,N,256]
    const float* neigh = (const float*)d_in[1];   // [T,N,5,256]
    const float* wag   = (const float*)d_in[2];   // [1,5]
    const float* wl    = (const float*)d_in[3];   // [256,256]
    const float* wr    = (const float*)d_in[4];   // [256,256]
    float* out         = (float*)d_out;           // [M,256]

    gat_prep_kernel<<<128, 256>>>(wl, wr);
    gat_mma_kernel<<<M_TOTAL / TILE_M, THREADS>>>(x, neigh, wag, out);
}

// round 17
// speedup vs baseline: 1.6380x; 1.6023x over previous
#include <cuda_runtime.h>
#include <cstdint>

// ---------------------------------------------------------------------------
// GAT fused: out[M,256] = x[M,256] @ w_l^T + (sum_k w_k * neigh[M,k,256]) @ w_r^T
// A[M,512] @ B[512,256], A = [x | aggr], B rows = [w_l ; w_r].
//
// R17: kill register spills (R7..R12 root cause) + restore cross-CTA overlap.
//  - CTA tile 64x128, THREADS=256, warp tile 32x32 -> acc = 32 regs/thread.
//    Demand ~110 regs -> no spills, 2 CTAs/SM (overlapping sync/drain phases).
//  - bid = (mtile<<1)|ntile: the two N-half CTAs of the same rows are adjacent
//    -> co-resident -> A re-read hits L2, DRAM stays at the 1.8 GB floor.
//  - B: prepass -> per-(chunk, N-half) pre-swizzled tf32 8KB blocks in g_B ->
//    cp.async one chunk ahead. A: LDG 2 ahead, wsum+cvt.rna+STS 1 ahead.
//  - Static 24KB smem/CTA, one __syncthreads per chunk, mma.sync m16n8k8 tf32.
// ---------------------------------------------------------------------------

#define M_TOTAL  262144      // T*N
#define DIN      256
#define DOUT     256
#define KNB      5
#define TILE_M   64
#define TILE_N   128
#define KC       16
#define NCH      32          // 512 / 16
#define THREADS  256

// Pre-converted, pre-swizzled B image: (32 chunks x 2 N-halves) x (128 x 16) tf32.
__device__ uint32_t g_B[NCH * 2 * TILE_N * KC];   // 512 KB

__device__ __forceinline__ uint32_t f2tf32(float f) {
    uint32_t u;
    asm("cvt.rna.tf32.f32 %0, %1;" : "=r"(u) : "f"(f));
    return u;
}

__device__ __forceinline__ void mma_tf32(float* d,
                                         uint32_t a0, uint32_t a1, uint32_t a2, uint32_t a3,
                                         uint32_t b0, uint32_t b1) {
    asm volatile(
        "mma.sync.aligned.m16n8k8.row.col.f32.tf32.tf32.f32 "
        "{%0,%1,%2,%3}, {%4,%5,%6,%7}, {%8,%9}, {%0,%1,%2,%3};"
        : "+f"(d[0]), "+f"(d[1]), "+f"(d[2]), "+f"(d[3])
        : "r"(a0), "r"(a1), "r"(a2), "r"(a3), "r"(b0), "r"(b1));
}

// Swizzle within a 16-float row: float4 group g of row r stored at g ^ ((r>>1)&3).
// Fragment loads conflict-free (validated R7/R12).
__device__ __forceinline__ int swz(int row, int col) {
    return row * KC + ((((col >> 2) ^ ((row >> 1) & 3)) << 2) | (col & 3));
}

__device__ __forceinline__ void cp_async16(uint32_t dst_smem, const void* src) {
    asm volatile("cp.async.cg.shared.global [%0], [%1], 16;"
                 :: "r"(dst_smem), "l"(src));
}

// ---- prepass: [w_l ; w_r] -> tf32, per-(chunk, N-half) swizzled 8KB blocks ----
__global__ void __launch_bounds__(256)
gat_prep_kernel(const float* __restrict__ wl, const float* __restrict__ wr)
{
    const int gid = blockIdx.x * 256 + threadIdx.x;   // 0..32767, one float4 each
    const int sub = gid >> 9;           // 0..63 : (chunk c)*2 + half h
    const int rem = gid & 511;
    const int c   = sub >> 1;
    const int h   = sub & 1;
    const int n   = rem >> 2;           // 0..127 (row within half)
    const int g   = rem & 3;            // float4 group 0..3
    const float* wsrc = (c < 16) ? wl : wr;
    float4 v = *(const float4*)(wsrc + (size_t)(h * TILE_N + n) * DIN + (c & 15) * KC + g * 4);
    uint4 pv = make_uint4(f2tf32(v.x), f2tf32(v.y), f2tf32(v.z), f2tf32(v.w));
    *(uint4*)&g_B[(size_t)sub * (TILE_N * KC) + swz(n, g * 4)] = pv;
}

// ---- main fused kernel ----
__global__ void __launch_bounds__(THREADS, 2)
gat_mma_kernel(const float* __restrict__ x, const float* __restrict__ neigh,
               const float* __restrict__ wag, float* __restrict__ out)
{
    __shared__ uint32_t sA[2][TILE_M * KC];   // 2 x 4 KB
    __shared__ uint32_t sB[2][TILE_N * KC];   // 2 x 8 KB   -> 24 KB total

    const int tid  = threadIdx.x;
    const int lane = tid & 31;
    const int wid  = tid >> 5;           // 0..7
    const int grp  = lane >> 2;          // 0..7
    const int qid  = lane & 3;           // 0..3
    const int warpM = wid >> 2;          // 0..1 (32 rows each)
    const int warpN = wid & 3;           // 0..3 (32 cols each)

    const int mtile = blockIdx.x >> 1;
    const int ntile = blockIdx.x & 1;

    const float w0 = wag[0], w1 = wag[1], w2 = wag[2], w3 = wag[3], w4 = wag[4];
    const size_t mbase = (size_t)mtile * TILE_M;

    // A loader: ONE float4 per thread per chunk (64 rows x 4 groups = 256).
    const int a_r = tid >> 2;            // row 0..63
    const int a_g = tid & 3;             // float4 group 0..3
    const int a_sts = swz(a_r, a_g * 4);

    const float* xrow = x + (mbase + (size_t)a_r) * DIN + a_g * 4;
    const float* nrow = neigh + (mbase + (size_t)a_r) * (KNB * DIN) + a_g * 4;
    const uint32_t* gB = g_B + (size_t)ntile * (TILE_N * KC);   // + sub*2 blocks

    float4 pre[KNB];   // raw prefetched A (x chunks: pre[0]; neigh: pre[0..4])

    float acc[2][4][4];
    #pragma unroll
    for (int i = 0; i < 2; ++i)
        #pragma unroll
        for (int j = 0; j < 4; ++j)
            #pragma unroll
            for (int q = 0; q < 4; ++q)
                acc[i][j][q] = 0.f;

    auto ldgA = [&](int c) {
        if (c < 16) {
            pre[0] = *(const float4*)(xrow + c * KC);
        } else {
            const int d = (c - 16) * KC;
            #pragma unroll
            for (int k = 0; k < KNB; ++k)
                pre[k] = *(const float4*)(nrow + d + k * DIN);
        }
    };
    auto stsA = [&](int c, int buf) {
        float4 v;
        if (c < 16) {
            v = pre[0];
        } else {
            v.x = w0*pre[0].x + w1*pre[1].x + w2*pre[2].x + w3*pre[3].x + w4*pre[4].x;
            v.y = w0*pre[0].y + w1*pre[1].y + w2*pre[2].y + w3*pre[3].y + w4*pre[4].y;
            v.z = w0*pre[0].z + w1*pre[1].z + w2*pre[2].z + w3*pre[3].z + w4*pre[4].z;
            v.w = w0*pre[0].w + w1*pre[1].w + w2*pre[2].w + w3*pre[3].w + w4*pre[4].w;
        }
        *(uint4*)&sA[buf][a_sts] =
            make_uint4(f2tf32(v.x), f2tf32(v.y), f2tf32(v.z), f2tf32(v.w));
    };
    auto cpB = [&](int c, int buf) {
        // 8 KB = 512 float4; 256 threads -> 2 cp.async of 16B each.
        const uint32_t* src = gB + (size_t)c * (2 * TILE_N * KC);
        uint32_t dst = (uint32_t)__cvta_generic_to_shared(&sB[buf][0]);
        cp_async16(dst + (uint32_t)tid * 16u, src + tid * 4);
        cp_async16(dst + (uint32_t)(tid + THREADS) * 16u, src + (tid + THREADS) * 4);
        asm volatile("cp.async.commit_group;" ::: "memory");
    };

    // ---- prologue ----
    ldgA(0);
    stsA(0, 0);
    cpB(0, 0);
    ldgA(1);

    // ---- main loop: ONE sync per chunk ----
    #pragma unroll 1
    for (int c = 0; c < NCH; ++c) {
        const int cur = c & 1, nxt = cur ^ 1;

        asm volatile("cp.async.wait_group 0;" ::: "memory");  // B(c) landed
        __syncthreads();   // A(c)+B(c) visible; all reads of [nxt] (c-1) done

        if (c + 1 < NCH) {
            cpB(c + 1, nxt);
            stsA(c + 1, nxt);
        }
        if (c + 2 < NCH) ldgA(c + 2);   // LDGs fly under the MMAs below

        #pragma unroll
        for (int ks = 0; ks < 2; ++ks) {
            const int k0 = 8 * ks;
            uint32_t a[2][4];
            #pragma unroll
            for (int i = 0; i < 2; ++i) {
                const int r = warpM * 32 + i * 16 + grp;
                a[i][0] = sA[cur][swz(r,     k0 + qid)];
                a[i][1] = sA[cur][swz(r + 8, k0 + qid)];
                a[i][2] = sA[cur][swz(r,     k0 + qid + 4)];
                a[i][3] = sA[cur][swz(r + 8, k0 + qid + 4)];
            }
            #pragma unroll
            for (int j = 0; j < 4; ++j) {
                const int n = warpN * 32 + j * 8 + grp;
                const uint32_t b0 = sB[cur][swz(n, k0 + qid)];
                const uint32_t b1 = sB[cur][swz(n, k0 + qid + 4)];
                mma_tf32(acc[0][j], a[0][0], a[0][1], a[0][2], a[0][3], b0, b1);
                mma_tf32(acc[1][j], a[1][0], a[1][1], a[1][2], a[1][3], b0, b1);
            }
        }
    }

    // ---- epilogue: m16n8 accumulator layout -> out ----
    #pragma unroll
    for (int i = 0; i < 2; ++i) {
        const size_t row = mbase + warpM * 32 + i * 16 + grp;
        #pragma unroll
        for (int j = 0; j < 4; ++j) {
            const int col = ntile * TILE_N + warpN * 32 + j * 8 + qid * 2;
            *(float2*)&out[row * DOUT + col] =
                make_float2(acc[i][j][0], acc[i][j][1]);
            *(float2*)&out[(row + 8) * DOUT + col] =
                make_float2(acc[i][j][2], acc[i][j][3]);
        }
    }
}

extern "C" void kernel_launch(void* const* d_in, const int* in_sizes, int n_in,
                              void* d_out, int out_size) {
    const float* x     = (const float*)d_in[0];   // [T,N,256]
    const float* neigh = (const float*)d_in[1];   // [T,N,5,256]
    const float* wag   = (const float*)d_in[2];   // [1,5]
    const float* wl    = (const float*)d_in[3];   // [256,256]
    const float* wr    = (const float*)d_in[4];   // [256,256]
    float* out         = (float*)d_out;           // [M,256]

    gat_prep_kernel<<<128, 256>>>(wl, wr);
    gat_mma_kernel<<<(M_TOTAL / TILE_M) * 2, THREADS>>>(x, neigh, wag, out);
}